// round 11
// baseline (speedup 1.0000x reference)
#include <cuda_runtime.h>
#include <cuda_fp16.h>
#include <math.h>

#define OUT_F 512
#define IN_F  1024
#define BATCH 256
#define NPAIR 128          // batch pairs (2 rows per half2 lane)
#define NSPLIT 32          // i-splits of 32 inputs each
#define JTILE  32          // output nodes per reduce block

// Scratch (device globals — no allocation allowed anywhere)
__device__ unsigned g_M[OUT_F * IN_F];           // select mask: 0 (edge -> x) / 0xFFFFFFFF (no_edge -> offset)
__device__ unsigned g_Xt[IN_F * NPAIR];          // x transposed+packed half2-as-u32: [i*128+p] = (x[2p][i], x[2p+1][i])
__device__ __half2  g_P[NSPLIT * OUT_F * NPAIR]; // partial reductions [s][j][p]

static __device__ __forceinline__ __half2 u2h2(unsigned v) {
    return *reinterpret_cast<__half2*>(&v);
}

// ---------------------------------------------------------------------------
// Kernel 1 (fused): blocks [0,2048): hard gumbel argmax -> 32-bit select mask.
//                   blocks [2048,2176): transpose/pack x into half2 [i][pair].
// Fast path: g(u) = -log(-log(u+eps)+eps) is strictly increasing in u, so for
// c0 == c1 the argmax decision is exactly u1 > u0 (ties -> index 0 = edge,
// matching jnp.argmax). General-c fallback keeps the bit-verified logf path.
// ---------------------------------------------------------------------------
__global__ __launch_bounds__(256) void prep_kernel(
    const float* __restrict__ etc, const float* __restrict__ noise,
    const float* __restrict__ x)
{
    const int bid = blockIdx.x;
    const int tid = threadIdx.x;
    __shared__ float ts[64][33];

    if (bid < 2048) {
        int e = bid * 256 + tid;                      // e = j*IN_F + i
        float2 c2 = reinterpret_cast<const float2*>(etc)[e];
        float2 n2 = reinterpret_cast<const float2*>(noise)[e];
        bool no_edge;
        if (c2.x == c2.y) {
            no_edge = n2.y > n2.x;                    // exact monotone shortcut
        } else {
            const float eps = 1e-10f;
            float g0 = -logf(-logf(n2.x + eps) + eps);
            float g1 = -logf(-logf(n2.y + eps) + eps);
            no_edge = (c2.y + g1) > (c2.x + g0);      // strict > : ties -> edge
        }
        g_M[e] = no_edge ? 0xFFFFFFFFu : 0u;
    } else {
        // transpose tile: 32 i-cols x 64 b-rows
        int b2 = bid - 2048;                          // 0..127
        int it = b2 & 31, bt = b2 >> 5;
        int i0 = it * 32, b0 = bt * 64;
        int col = tid & 31, rw = tid >> 5;
        #pragma unroll
        for (int k = 0; k < 8; k++)
            ts[rw + k * 8][col] = x[(b0 + rw + k * 8) * IN_F + i0 + col];  // coalesced
        __syncthreads();
        #pragma unroll
        for (int k = 0; k < 4; k++) {
            int idx = tid + k * 256;                  // 0..1023
            int il = idx >> 5, pl = idx & 31;
            float lo = ts[2 * pl + 0][il];
            float hi = ts[2 * pl + 1][il];
            __half2 h = __floats2half2_rn(lo, hi);
            g_Xt[(i0 + il) * NPAIR + (b0 >> 1) + pl] = *reinterpret_cast<unsigned*>(&h);
        }
    }
}

// ---------------------------------------------------------------------------
// Kernel 2: packed select + min/max partial reduction.
// Per half2 element: 1 LOP3 (alu pipe) + 1 HMNMX2 (fma pipe) -> dual-issue,
// 0.5 issue slots per scalar element. Select constant is the EXACT reference
// no-edge offset (2.0 min-nodes / -1.0 max-nodes), so no clamp is needed and
// accumulator init = the identity offset itself.
// ---------------------------------------------------------------------------
__global__ __launch_bounds__(128) void reduce_kernel()
{
    __shared__ unsigned Ms[JTILE][32];   // mask tile [j][i], rows = 128B

    const int s  = blockIdx.x;           // 0..31
    const int jt = blockIdx.y;           // 0..15
    const int i0 = s * 32;
    const int j0 = jt * JTILE;
    const int p  = threadIdx.x;          // batch-pair index

    // Stage mask tile (1024 u32; 8 per thread, coalesced 128B rows)
    #pragma unroll
    for (int k = 0; k < 8; k++) {
        int idx = p + k * 128;
        int jl = idx >> 5, il = idx & 31;
        Ms[jl][il] = g_M[(j0 + jl) * IN_F + i0 + il];
    }
    // Cache this pair's 32 x values in registers (reused across all 32 j)
    unsigned xr[32];
    #pragma unroll
    for (int k = 0; k < 32; k++)
        xr[k] = g_Xt[(i0 + k) * NPAIR + p];          // 128B coalesced per warp
    __syncthreads();

    const unsigned OFFP = 0x40004000u;               // half2(+2.0, +2.0) : min-node no-edge value
    const unsigned OFFN = 0xBC00BC00u;               // half2(-1.0, -1.0) : max-node no-edge value
    const __half2 PI = u2h2(OFFP);                   // min identity == masked value
    const __half2 NI = u2h2(OFFN);                   // max identity == masked value

    // (min-node, max-node) pairs; jj even -> global j even -> t-norm (min)
    #pragma unroll 1
    for (int jj = 0; jj < JTILE; jj += 2) {
        __half2 m0 = PI, m1 = PI;                    // 4 chains for ILP
        __half2 M0 = NI, M1 = NI;
        const uint4* a0p = reinterpret_cast<const uint4*>(&Ms[jj][0]);
        const uint4* a1p = reinterpret_cast<const uint4*>(&Ms[jj + 1][0]);
        #pragma unroll
        for (int q = 0; q < 8; q++) {
            uint4 a0 = a0p[q];                       // LDS.128 uniform -> broadcast
            uint4 a1 = a1p[q];
            m0 = __hmin2(m0, u2h2((a0.x & OFFP) | (~a0.x & xr[4 * q + 0])));  // LOP3 + HMNMX2
            m1 = __hmin2(m1, u2h2((a0.y & OFFP) | (~a0.y & xr[4 * q + 1])));
            m0 = __hmin2(m0, u2h2((a0.z & OFFP) | (~a0.z & xr[4 * q + 2])));
            m1 = __hmin2(m1, u2h2((a0.w & OFFP) | (~a0.w & xr[4 * q + 3])));
            M0 = __hmax2(M0, u2h2((a1.x & OFFN) | (~a1.x & xr[4 * q + 0])));
            M1 = __hmax2(M1, u2h2((a1.y & OFFN) | (~a1.y & xr[4 * q + 1])));
            M0 = __hmax2(M0, u2h2((a1.z & OFFN) | (~a1.z & xr[4 * q + 2])));
            M1 = __hmax2(M1, u2h2((a1.w & OFFN) | (~a1.w & xr[4 * q + 3])));
        }
        g_P[(s * OUT_F + j0 + jj + 0) * NPAIR + p] = __hmin2(m0, m1);  // coalesced
        g_P[(s * OUT_F + j0 + jj + 1) * NPAIR + p] = __hmax2(M0, M1);
    }
}

// ---------------------------------------------------------------------------
// Kernel 3: combine the NSPLIT partials (packed), unpack to fp32. No clamp
// needed: masked lanes already carry the exact identity offsets.
// ---------------------------------------------------------------------------
__global__ __launch_bounds__(256) void combine_kernel(float* __restrict__ out)
{
    int g = blockIdx.x * blockDim.x + threadIdx.x;   // 65536 threads
    int j = g >> 7;                                  // 0..511 (warp-uniform)
    int p = g & (NPAIR - 1);
    if ((j & 1) == 0) {
        __half2 acc = __float2half2_rn(2.0f);
        #pragma unroll
        for (int s = 0; s < NSPLIT; s++)
            acc = __hmin2(acc, g_P[(s * OUT_F + j) * NPAIR + p]);
        out[(2 * p + 0) * OUT_F + j] = __low2float(acc);
        out[(2 * p + 1) * OUT_F + j] = __high2float(acc);
    } else {
        __half2 acc = __float2half2_rn(-1.0f);
        #pragma unroll
        for (int s = 0; s < NSPLIT; s++)
            acc = __hmax2(acc, g_P[(s * OUT_F + j) * NPAIR + p]);
        out[(2 * p + 0) * OUT_F + j] = __low2float(acc);
        out[(2 * p + 1) * OUT_F + j] = __high2float(acc);
    }
}

// ---------------------------------------------------------------------------
extern "C" void kernel_launch(void* const* d_in, const int* in_sizes, int n_in,
                              void* d_out, int out_size)
{
    const float* x     = (const float*)d_in[0];   // [256, 1024]
    const float* etc   = (const float*)d_in[1];   // [512, 1024, 2]
    const float* noise = (const float*)d_in[2];   // [512, 1024, 2]
    float* out = (float*)d_out;                   // [256, 512]

    prep_kernel<<<2048 + 128, 256>>>(etc, noise, x);
    reduce_kernel<<<dim3(NSPLIT, OUT_F / JTILE), 128>>>();
    combine_kernel<<<(OUT_F * NPAIR + 255) / 256, 256>>>(out);
}